// round 17
// baseline (speedup 1.0000x reference)
#include <cuda_runtime.h>

// Problem constants
#define Bg    16
#define NPGc  2048
#define NNc   32768      // Bg * NPGc
#define CINc  64
#define HIDc  128
#define KCc   32
#define EEc   524288

// ---------------- device scratch ----------------
__device__ float4 g_hlin4[NNc*HIDc/4];    // xn @ W1 (pre-aggregation)
#define g_hlin ((float*)g_hlin4)

__device__ int   g_src[EEc];
__device__ int   g_dst[EEc];
__device__ int   g_rank[EEc];             // rank of edge within its dst bucket
__device__ int   g_csrc[EEc];             // CSR column (src) indices, grouped by dst
__device__ int   g_degi[NNc];             // in-degree (int)
__device__ int   g_rowptr[NNc];           // CSR row starts
__device__ int   g_counter;               // scan base allocator

__device__ float g_gnsum[Bg*CINc];
__device__ float g_gnsq[Bg*CINc];
__device__ float g_dis[NNc];              // rsqrt(in_deg + 1)
__device__ float g_degsrc[NNc];           // DMoN degrees (out-degree)
__device__ float g_ecount[Bg];
__device__ float g_trace[Bg];             // sum_e dot(s_src, s_dst)
__device__ float g_sx[Bg*KCc*HIDc];       // S^T X per graph
__device__ float g_ss[Bg*KCc*KCc];        // S^T S per graph
__device__ float g_ca[Bg*KCc];            // S^T degrees
__device__ float g_cs[Bg*KCc];            // cluster sizes

// ---------------- f32x2 helpers ----------------
__device__ __forceinline__ unsigned long long f2pack(float x, float y) {
    unsigned long long r;
    asm("mov.b64 %0, {%1, %2};" : "=l"(r) : "f"(x), "f"(y));
    return r;
}
__device__ __forceinline__ unsigned long long ffma2(unsigned long long a,
                                                    unsigned long long b,
                                                    unsigned long long c) {
    unsigned long long d;
    asm("fma.rn.f32x2 %0, %1, %2, %3;" : "=l"(d) : "l"(a), "l"(b), "l"(c));
    return d;
}
__device__ __forceinline__ float2 f2unpack(unsigned long long v) {
    float2 f;
    asm("mov.b64 {%0, %1}, %2;" : "=f"(f.x), "=f"(f.y) : "l"(v));
    return f;
}

// ---------------- K0a: zero edge-chain state (main stream) ----------------
__global__ __launch_bounds__(256) void k_zero_edge() {
    int i0 = blockIdx.x * blockDim.x + threadIdx.x;
    int stride = gridDim.x * blockDim.x;
    for (int i = i0; i < NNc; i += stride) { g_degi[i] = 0; g_degsrc[i] = 0.f; }
    if (i0 < Bg) g_ecount[i0] = 0.f;
    if (i0 == 0) g_counter = 0;
}

// ---------------- K0b: zero accumulators (s2, off edge critical path) ----------------
__global__ __launch_bounds__(256) void k_zero_acc() {
    int i0 = blockIdx.x * blockDim.x + threadIdx.x;
    int stride = gridDim.x * blockDim.x;
    for (int i = i0; i < Bg*KCc*HIDc; i += stride) g_sx[i] = 0.f;
    for (int i = i0; i < Bg*KCc*KCc; i += stride) g_ss[i] = 0.f;
    for (int i = i0; i < Bg*KCc; i += stride) { g_ca[i] = 0.f; g_cs[i] = 0.f; }
    for (int i = i0; i < Bg*CINc; i += stride) { g_gnsum[i] = 0.f; g_gnsq[i] = 0.f; }
    if (i0 < Bg) g_trace[i0] = 0.f;
}

// ---------------- K1: edge convert + in-degree + in-bucket rank (ILP 2) ----------------
__global__ __launch_bounds__(256) void k_convert_deg(const void* __restrict__ ebuf) {
    __shared__ int nz;
    int t = threadIdx.x;
    if (t == 0) nz = 0;
    __syncthreads();
    int e0 = blockIdx.x * 256 + t;   // grid 1024 -> 2 edges/thread
    const int* w32 = (const int*)ebuf;
    unsigned any = __ballot_sync(0xffffffffu, w32[e0 * 2 + 1] != 0);
    if ((t & 31) == 0 && any) atomicOr(&nz, 1);
    __syncthreads();
    int is32 = nz;
#pragma unroll
    for (int u = 0; u < 2; u++) {
        int e = e0 + u * (EEc / 2);
        int s, d;
        if (is32 == 0) {   // int64
            const long long* p = (const long long*)ebuf;
            s = (int)p[e] & (NNc - 1);
            d = (int)p[EEc + e] & (NNc - 1);
        } else {           // int32
            s = w32[e] & (NNc - 1);
            d = w32[EEc + e] & (NNc - 1);
        }
        g_src[e] = s;
        g_dst[e] = d;
        g_rank[e] = atomicAdd(&g_degi[d], 1);
    }
}

// ---------------- K2: single-pass scan (atomic base) + dis ----------------
__global__ __launch_bounds__(256) void k_scan() {
    __shared__ int sm[256];
    __shared__ int base;
    int t = threadIdx.x;
    int n = blockIdx.x * 256 + t;
    int d = g_degi[n];
    sm[t] = d;
    __syncthreads();
    for (int o = 1; o < 256; o <<= 1) {
        int a = (t >= o) ? sm[t - o] : 0;
        __syncthreads();
        sm[t] += a;
        __syncthreads();
    }
    if (t == 255) base = atomicAdd(&g_counter, sm[255]);
    __syncthreads();
    g_rowptr[n] = base + sm[t] - d;
    g_dis[n] = rsqrtf((float)d + 1.f);
}

// ---------------- K3: atomic-free CSR fill + out-degree histogram ----------------
__global__ __launch_bounds__(256) void k_fill() {
    int e = blockIdx.x * 256 + threadIdx.x;   // grid 2048
    int d = g_dst[e];
    int s = g_src[e];
    g_csrc[g_rowptr[d] + g_rank[e]] = s;
    atomicAdd(&g_degsrc[s], 1.f);
}

// ---------------- K4: GraphNorm partial sums (grid (Bg,32), 64 rows/block) ----------------
__global__ __launch_bounds__(256) void k_gn_part(const float* __restrict__ x) {
    __shared__ float ssum[256], ssq[256];
    int b = blockIdx.x;
    int c = threadIdx.x & 63, r0 = threadIdx.x >> 6;
    const float* xb = x + (size_t)b * NPGc * CINc + (size_t)blockIdx.y * 64 * CINc;
    float s = 0.f, q = 0.f;
    for (int r = r0; r < 64; r += 4) {
        float v = xb[r * CINc + c];
        s += v; q += v * v;
    }
    ssum[threadIdx.x] = s; ssq[threadIdx.x] = q;
    __syncthreads();
    if (threadIdx.x < 64) {
        s = ssum[c] + ssum[c+64] + ssum[c+128] + ssum[c+192];
        q = ssq[c] + ssq[c+64] + ssq[c+128] + ssq[c+192];
        atomicAdd(&g_gnsum[b*CINc + c], s);
        atomicAdd(&g_gnsq[b*CINc + c], q);
    }
}

// ---------------- K5: GN finalize (per-block) + apply + GEMM (f32x2) ----------------
__global__ __launch_bounds__(256) void k_gemm1(const float* __restrict__ x,
                                               const float* __restrict__ gnw,
                                               const float* __restrict__ gnb,
                                               const float* __restrict__ gms,
                                               const float* __restrict__ W1) {
    __shared__ float Ws[CINc][HIDc];     // 32 KB
    __shared__ float Xs[32][CINc + 1];   // 8.1 KB
    __shared__ float sshift[CINc], sscale[CINc];
    int n0 = blockIdx.x * 32;
    int b = n0 / NPGc;
    if (threadIdx.x < CINc) {
        int c = threadIdx.x;
        float mean = g_gnsum[b*CINc + c] * (1.f / NPGc);
        float ms = gms[c];
        float var = g_gnsq[b*CINc + c] * (1.f / NPGc)
                  - 2.f * ms * mean * mean + ms * ms * mean * mean;
        sshift[c] = mean * ms;
        sscale[c] = gnw[c] * rsqrtf(var + 1e-5f);
    }
    for (int i = threadIdx.x; i < CINc * HIDc; i += 256)
        Ws[i >> 7][i & 127] = W1[i];
    __syncthreads();
    for (int i = threadIdx.x; i < 32 * CINc; i += 256) {
        int r = i >> 6, c = i & 63;
        float v = x[(size_t)(n0 + r) * CINc + c];
        Xs[r][c] = (v - sshift[c]) * sscale[c] + gnb[c];
    }
    __syncthreads();

    int q = threadIdx.x & 7;
    int jg = threadIdx.x >> 3;
    unsigned long long acc2[4][2];
#pragma unroll
    for (int i = 0; i < 4; i++) { acc2[i][0] = 0ull; acc2[i][1] = 0ull; }

    for (int k = 0; k < CINc; k++) {
        unsigned long long w01 = *(const unsigned long long*)&Ws[k][jg*4];
        unsigned long long w23 = *(const unsigned long long*)&Ws[k][jg*4+2];
#pragma unroll
        for (int i = 0; i < 4; i++) {
            float a = Xs[q*4+i][k];
            unsigned long long a2 = f2pack(a, a);
            acc2[i][0] = ffma2(a2, w01, acc2[i][0]);
            acc2[i][1] = ffma2(a2, w23, acc2[i][1]);
        }
    }
#pragma unroll
    for (int i = 0; i < 4; i++) {
        float2 f01 = f2unpack(acc2[i][0]);
        float2 f23 = f2unpack(acc2[i][1]);
        g_hlin4[(size_t)(n0 + q*4 + i) * (HIDc/4) + jg] =
            make_float4(f01.x, f01.y, f23.x, f23.y);
    }
}

// ---------------- K6: FUSED gather + finalize-h + softmax + node reductions ----------------
__global__ __launch_bounds__(256) void k_fin_red(const float* __restrict__ b1,
                                                 const float* __restrict__ Wp,
                                                 const float* __restrict__ bp,
                                                 float* __restrict__ out_s) {
    __shared__ float Wps[HIDc * KCc];  // 16 KB
    __shared__ float sH[32][HIDc];     // 16 KB
    __shared__ float sS[16][KCc];      // 2 KB
    __shared__ float sD[16];
    __shared__ float b1s[HIDc];
    __shared__ float bps[KCc];
    int tid = threadIdx.x;
    int b = blockIdx.x;
    int n0 = b * NPGc + blockIdx.y * 32;
    for (int i = tid; i < HIDc * KCc; i += 256) Wps[i] = Wp[i];
    if (tid < HIDc) b1s[tid] = b1[tid];
    if (tid < KCc)  bps[tid] = bp[tid];
    __syncthreads();

    int warp = tid >> 5, lane = tid & 31;

    // ---- Phase A: gather 4 nodes per warp ----
#pragma unroll
    for (int u = 0; u < 4; u++) {
        int nl = warp * 4 + u;
        int n = n0 + nl;
        int rs  = g_rowptr[n];
        int deg = g_degi[n];
        float disd = g_dis[n];
        unsigned long long a01 = 0ull, a23 = 0ull;
        for (int base = 0; base < deg; base += 32) {
            int l = base + lane;
            int idx = 0; float cl = 0.f;
            if (l < deg) {
                idx = g_csrc[rs + l];
                cl = disd * g_dis[idx];
            }
            int cnt = min(32, deg - base);
#pragma unroll 4
            for (int i = 0; i < cnt; i++) {
                int s  = __shfl_sync(0xffffffffu, idx, i);
                float c = __shfl_sync(0xffffffffu, cl, i);
                float4 v = g_hlin4[(size_t)s * (HIDc/4) + lane];
                unsigned long long c2 = f2pack(c, c);
                a01 = ffma2(c2, f2pack(v.x, v.y), a01);
                a23 = ffma2(c2, f2pack(v.z, v.w), a23);
            }
        }
        float4 hv = g_hlin4[(size_t)n * (HIDc/4) + lane];
        float dd = disd * disd;
        float2 f01 = f2unpack(a01), f23 = f2unpack(a23);
        float4 r;
        r.x = fmaxf(f01.x + dd * hv.x + b1s[lane*4+0], 0.f);
        r.y = fmaxf(f01.y + dd * hv.y + b1s[lane*4+1], 0.f);
        r.z = fmaxf(f23.x + dd * hv.z + b1s[lane*4+2], 0.f);
        r.w = fmaxf(f23.y + dd * hv.w + b1s[lane*4+3], 0.f);
        *(float4*)&sH[nl][lane*4] = r;
    }
    __syncthreads();

    // ---- Phase B: softmax + reductions over 2 tiles of 16 nodes ----
    int k = tid >> 3, j8 = tid & 7;
    unsigned long long accx2[8];
#pragma unroll
    for (int i = 0; i < 8; i++) accx2[i] = 0ull;
    float accss[4] = {0.f, 0.f, 0.f, 0.f};
    float accca = 0.f, acccs = 0.f, eacc = 0.f;

    for (int tile = 0; tile < 2; tile++) {
        if (tile > 0) __syncthreads();
        if (tid < 16) sD[tid] = g_degsrc[n0 + tile * 16 + tid];
#pragma unroll
        for (int u = 0; u < 2; u++) {
            int nl = warp * 2 + u;
            int gl = tile * 16 + nl;
            float acc = bps[lane];
#pragma unroll 8
            for (int j = 0; j < HIDc; j++)
                acc += sH[gl][j] * Wps[j * KCc + lane];
            float m = acc;
#pragma unroll
            for (int o = 16; o; o >>= 1) m = fmaxf(m, __shfl_xor_sync(0xffffffffu, m, o));
            float e = expf(acc - m);
            float sum = e;
#pragma unroll
            for (int o = 16; o; o >>= 1) sum += __shfl_xor_sync(0xffffffffu, sum, o);
            float sv = e / sum;
            sS[nl][lane] = sv;
            out_s[(size_t)(n0 + gl) * KCc + lane] = sv;
        }
        __syncthreads();
        if (tid < 16) eacc += sD[tid];
#pragma unroll 4
        for (int nn = 0; nn < 16; nn++) {
            float sk = sS[nn][k];
            unsigned long long sk2 = f2pack(sk, sk);
            const unsigned long long* row = (const unsigned long long*)&sH[tile*16 + nn][0];
#pragma unroll
            for (int jj = 0; jj < 8; jj++)
                accx2[jj] = ffma2(sk2, row[j8 + jj * 8], accx2[jj]);
#pragma unroll
            for (int i = 0; i < 4; i++) {
                int idx = tid * 4 + i;
                accss[i] += sS[nn][idx >> 5] * sS[nn][idx & 31];
            }
            if (tid < 32) {
                float sv = sS[nn][tid];
                accca += sv * sD[nn];
                acccs += sv;
            }
        }
    }
#pragma unroll
    for (int jj = 0; jj < 8; jj++) {
        float2 r = f2unpack(accx2[jj]);
        atomicAdd(&g_sx[b*KCc*HIDc + k*HIDc + 2*j8 + 16*jj], r.x);
        atomicAdd(&g_sx[b*KCc*HIDc + k*HIDc + 2*j8 + 16*jj + 1], r.y);
    }
#pragma unroll
    for (int i = 0; i < 4; i++)
        atomicAdd(&g_ss[b*KCc*KCc + tid*4 + i], accss[i]);
    if (tid < 32) {
        atomicAdd(&g_ca[b*KCc + tid], accca);
        atomicAdd(&g_cs[b*KCc + tid], acccs);
    }
    if (tid < 16) atomicAdd(&g_ecount[b], eacc);
}

// ---------------- K8: spectral trace via CSR ----------------
__global__ __launch_bounds__(256) void k_trace(const float* __restrict__ s) {
    __shared__ float sacc;
    if (threadIdx.x == 0) sacc = 0.f;
    __syncthreads();
    int n = (blockIdx.x * 256 + threadIdx.x) >> 5;
    int lane = threadIdx.x & 31;
    int rs  = g_rowptr[n];
    int deg = g_degi[n];
    float accv = 0.f;
    for (int base = 0; base < deg; base += 32) {
        int l = base + lane;
        int idx = (l < deg) ? g_csrc[rs + l] : 0;
        int cnt = min(32, deg - base);
#pragma unroll 4
        for (int i = 0; i < cnt; i++) {
            int sn = __shfl_sync(0xffffffffu, idx, i);
            accv += s[(size_t)sn * KCc + lane];
        }
    }
    float p = accv * s[(size_t)n * KCc + lane];
#pragma unroll
    for (int o = 16; o; o >>= 1) p += __shfl_xor_sync(0xffffffffu, p, o);
    if (lane == 0) atomicAdd(&sacc, p);
    __syncthreads();
    if (threadIdx.x == 0) atomicAdd(&g_trace[(blockIdx.x * 8) >> 11], sacc);
}

// ---------------- K9: losses ----------------
__global__ __launch_bounds__(512) void k_losses(float* __restrict__ out_loss) {
    __shared__ float bl[Bg];
    int w = threadIdx.x >> 5, lane = threadIdx.x & 31;
    if (w < Bg) {
        int b = w;
        float m = g_ecount[b] * 0.5f;
        float q = 0.f;
        for (int i = 0; i < 32; i++) {
            float v = g_ss[b*1024 + i*32 + lane];
            q += v * v;
        }
#pragma unroll
        for (int o = 16; o; o >>= 1) q += __shfl_xor_sync(0xffffffffu, q, o);
        float nrm = sqrtf(q);
        float inv_sk = rsqrtf((float)KCc);
        float oo = 0.f;
        for (int i = 0; i < 32; i++) {
            float v = g_ss[b*1024 + i*32 + lane] / nrm - ((i == lane) ? inv_sk : 0.f);
            oo += v * v;
        }
#pragma unroll
        for (int o = 16; o; o >>= 1) oo += __shfl_xor_sync(0xffffffffu, oo, o);
        float cav = g_ca[b*KCc + lane];
        float ca2 = cav * cav;
#pragma unroll
        for (int o = 16; o; o >>= 1) ca2 += __shfl_xor_sync(0xffffffffu, ca2, o);
        float csv = g_cs[b*KCc + lane];
        float cs2 = csv * csv;
#pragma unroll
        for (int o = 16; o; o >>= 1) cs2 += __shfl_xor_sync(0xffffffffu, cs2, o);
        if (lane == 0) {
            float spec = -(g_trace[b] - ca2 / (2.f * m)) / (2.f * m);
            float ortho = sqrtf(oo);
            float clus = sqrtf(cs2) / (float)NPGc * sqrtf((float)KCc) - 1.f;
            bl[b] = spec + ortho + clus;
        }
    }
    __syncthreads();
    if (threadIdx.x == 0) {
        float t = 0.f;
        for (int i = 0; i < Bg; i++) t += bl[i];
        out_loss[0] = t / (float)Bg;
    }
}

// ---------------- K10: selu + log_softmax of out_x ----------------
__global__ __launch_bounds__(128) void k_outx(float* __restrict__ out) {
    __shared__ float redm[4], reds[4];
    int row = blockIdx.x;
    int t = threadIdx.x;
    int warp = t >> 5, lane = t & 31;
    float v = g_sx[row * HIDc + t];
    const float sc = 1.0507009873554805f, al = 1.6732632423543772f;
    v = (v > 0.f) ? sc * v : sc * al * (expf(v) - 1.f);
    float mx = v;
#pragma unroll
    for (int o = 16; o; o >>= 1) mx = fmaxf(mx, __shfl_xor_sync(0xffffffffu, mx, o));
    if (lane == 0) redm[warp] = mx;
    __syncthreads();
    mx = fmaxf(fmaxf(redm[0], redm[1]), fmaxf(redm[2], redm[3]));
    float e = expf(v - mx);
    float sum = e;
#pragma unroll
    for (int o = 16; o; o >>= 1) sum += __shfl_xor_sync(0xffffffffu, sum, o);
    if (lane == 0) reds[warp] = sum;
    __syncthreads();
    sum = reds[0] + reds[1] + reds[2] + reds[3];
    out[row * HIDc + t] = v - mx - logf(sum);
}

// ---------------- launch (two-stream fork-join, twice; split zero) ----------------
extern "C" void kernel_launch(void* const* d_in, const int* in_sizes, int n_in,
                              void* d_out, int out_size) {
    int i_x = 0, i_W1 = 4, i_b1 = 5, i_Wp = 6, i_bp = 7, i_ei = 8;
    for (int i = 0; i < n_in; i++) {
        int sz = in_sizes[i];
        if (sz == NNc * CINc)       i_x  = i;
        else if (sz == CINc * HIDc) i_W1 = i;
        else if (sz == HIDc)        i_b1 = i;
        else if (sz == HIDc * KCc)  i_Wp = i;
        else if (sz == KCc)         i_bp = i;
        else if (sz == 2 * EEc)     i_ei = i;
    }
    const float* x   = (const float*)d_in[i_x];
    const float* gnw = (const float*)d_in[1];
    const float* gnb = (const float*)d_in[2];
    const float* gms = (const float*)d_in[3];
    const float* W1  = (const float*)d_in[i_W1];
    const float* b1  = (const float*)d_in[i_b1];
    const float* Wp  = (const float*)d_in[i_Wp];
    const float* bp  = (const float*)d_in[i_bp];
    const void*  ei  = d_in[i_ei];

    float* out = (float*)d_out;
    float* out_loss = out + Bg*KCc*HIDc;          // 65536
    float* out_s    = out + Bg*KCc*HIDc + 1;      // 65537

    cudaStream_t s2;
    cudaEvent_t evFork, evJoin, evFin, evTail;
    cudaStreamCreateWithFlags(&s2, cudaStreamNonBlocking);
    cudaEventCreateWithFlags(&evFork, cudaEventDisableTiming);
    cudaEventCreateWithFlags(&evJoin, cudaEventDisableTiming);
    cudaEventCreateWithFlags(&evFin,  cudaEventDisableTiming);
    cudaEventCreateWithFlags(&evTail, cudaEventDisableTiming);

    // fork immediately: s2 zeroes accumulators then runs the x chain;
    // main zeroes edge state then runs the edge chain.
    cudaEventRecord(evFork, 0);
    cudaStreamWaitEvent(s2, evFork, 0);

    k_zero_acc<<<512, 256, 0, s2>>>();
    k_gn_part<<<dim3(Bg, 32), 256, 0, s2>>>(x);
    k_gemm1<<<NNc/32, 256, 0, s2>>>(x, gnw, gnb, gms, W1);
    cudaEventRecord(evJoin, s2);

    k_zero_edge<<<256, 256>>>();
    k_convert_deg<<<1024, 256>>>(ei);
    k_scan<<<NNc/256, 256>>>();
    k_fill<<<EEc/256, 256>>>();

    // join: fused fin_red needs both chains
    cudaStreamWaitEvent(0, evJoin, 0);
    k_fin_red<<<dim3(Bg, 64), 256>>>(b1, Wp, bp, out_s);

    // second fork: trace+losses (s2) overlap outx (main)
    cudaEventRecord(evFin, 0);
    cudaStreamWaitEvent(s2, evFin, 0);
    k_trace<<<NNc/8, 256, 0, s2>>>(out_s);
    k_losses<<<1, 512, 0, s2>>>(out_loss);
    cudaEventRecord(evTail, s2);

    k_outx<<<Bg*KCc, 128>>>(out);
    cudaStreamWaitEvent(0, evTail, 0);

    cudaEventDestroy(evFork);
    cudaEventDestroy(evJoin);
    cudaEventDestroy(evFin);
    cudaEventDestroy(evTail);
    cudaStreamDestroy(s2);
}